// round 2
// baseline (speedup 1.0000x reference)
#include <cuda_runtime.h>

#define NB      2048        // histogram bins
#define EPSF    1e-7f
#define CHUNKS  8
#define NTHR    512
#define NPIX    409600      // 640*640
#define BATCH   16
#define FIXSH   4194304.0f  // 2^22 fixed point
#define CNT_SHIFT 42

// ---------------- device scratch (no allocation allowed) ----------------
__device__ unsigned long long g_hist_s[BATCH][NB];
__device__ unsigned long long g_hist_b[BATCH][NB];
__device__ int   g_pos_cnt[BATCH];
__device__ float g_pos_loss_s[BATCH];
__device__ float g_pos_loss_b[BATCH];
__device__ float g_thr_l1[BATCH];
__device__ int   g_thr_cnt[BATCH];
__device__ float g_ls[BATCH], g_lb[BATCH], g_lt[BATCH];

// ---------------- zero scratch ----------------
__global__ void zero_kernel() {
    int idx = blockIdx.x * blockDim.x + threadIdx.x;
    if (idx < BATCH * NB) {
        ((unsigned long long*)g_hist_s)[idx] = 0ULL;
        ((unsigned long long*)g_hist_b)[idx] = 0ULL;
    }
    if (idx < BATCH) {
        g_pos_cnt[idx] = 0; g_pos_loss_s[idx] = 0.f; g_pos_loss_b[idx] = 0.f;
        g_thr_l1[idx] = 0.f; g_thr_cnt[idx] = 0;
    }
}

__device__ __forceinline__ unsigned long long pack1(float v) {
    // one element: count=1 in high bits, fixed-point value in low 42 bits
    return (1ULL << CNT_SHIFT) + (unsigned long long)(v * FIXSH + 0.5f);
}

// ---------------- main fused pass ----------------
__global__ void __launch_bounds__(NTHR) hist_kernel(const float* __restrict__ outputs,
                                                    const float* __restrict__ gts,
                                                    const float* __restrict__ gtt) {
    __shared__ unsigned long long hs[NB];
    __shared__ unsigned long long hb[NB];
    __shared__ float sf[3];   // pos_loss_s, pos_loss_b, thr_l1
    __shared__ int   si[2];   // pos_cnt, thr_cnt

    const int s     = blockIdx.x >> 3;
    const int chunk = blockIdx.x & 7;
    const int tid   = threadIdx.x;

    for (int j = tid; j < NB; j += NTHR) { hs[j] = 0ULL; hb[j] = 0ULL; }
    if (tid < 3) sf[tid] = 0.f;
    if (tid < 2) si[tid] = 0;
    __syncthreads();

    const int base = chunk * (NPIX / CHUNKS); // 51200, 16B aligned in floats
    const float4* ps  = (const float4*)(outputs + (size_t)(s * 3 + 0) * NPIX + base);
    const float4* pt  = (const float4*)(outputs + (size_t)(s * 3 + 1) * NPIX + base);
    const float4* pb  = (const float4*)(outputs + (size_t)(s * 3 + 2) * NPIX + base);
    const float4* pgs = (const float4*)(gts + (size_t)s * NPIX + base);
    const float4* pgt = (const float4*)(gtt + (size_t)s * NPIX + base);

    int   pos_cnt = 0, thr_cnt = 0;
    float pls = 0.f, plb = 0.f, tl1 = 0.f;

    const int NIT = (NPIX / CHUNKS) / 4 / NTHR;  // 25
    for (int it = 0; it < NIT; it++) {
        const int i = it * NTHR + tid;
        float4 vs = ps[i], vt = pt[i], vb = pb[i], vgs = pgs[i], vgt = pgt[i];
        const float* fs  = (const float*)&vs;
        const float* ft  = (const float*)&vt;
        const float* fb  = (const float*)&vb;
        const float* fgs = (const float*)&vgs;
        const float* fgt = (const float*)&vgt;
#pragma unroll
        for (int l = 0; l < 4; l++) {
            const float g   = fgs[l];
            const bool  pos = (g > 0.5f);

            // shrink map: score = p
            float p = fminf(fmaxf(fs[l], EPSF), 1.f - EPSF);
            if (pos) { pos_cnt++; pls -= __logf(p); }
            else {
                int b = min((int)(p * (float)NB), NB - 1);
                atomicAdd(&hs[b], pack1(p));
            }

            // binary map: score = sigmoid(x), monotone in x -> bin on x
            float x = fb[l];
            if (pos) { plb += __logf(1.0f + __expf(-x)); }  // -log(sigmoid(x))
            else {
                float xc = fminf(fmaxf(x, 0.0f), 0.999999f);
                int b = min((int)(xc * (float)NB), NB - 1);
                atomicAdd(&hb[b], pack1(xc));
            }

            // threshold L1
            const float gt = fgt[l];
            if (gt > 0.f || g > 0.f) { thr_cnt++; tl1 += fabsf(ft[l] - gt); }
        }
    }

    // warp reduce then shared accumulate
#pragma unroll
    for (int off = 16; off; off >>= 1) {
        pos_cnt += __shfl_down_sync(0xffffffffu, pos_cnt, off);
        thr_cnt += __shfl_down_sync(0xffffffffu, thr_cnt, off);
        pls += __shfl_down_sync(0xffffffffu, pls, off);
        plb += __shfl_down_sync(0xffffffffu, plb, off);
        tl1 += __shfl_down_sync(0xffffffffu, tl1, off);
    }
    if ((tid & 31) == 0) {
        atomicAdd(&si[0], pos_cnt); atomicAdd(&si[1], thr_cnt);
        atomicAdd(&sf[0], pls); atomicAdd(&sf[1], plb); atomicAdd(&sf[2], tl1);
    }
    __syncthreads();
    if (tid == 0) {
        atomicAdd(&g_pos_cnt[s], si[0]);
        atomicAdd(&g_thr_cnt[s], si[1]);
        atomicAdd(&g_pos_loss_s[s], sf[0]);
        atomicAdd(&g_pos_loss_b[s], sf[1]);
        atomicAdd(&g_thr_l1[s], sf[2]);
    }

    // merge histograms to global
    for (int j = tid; j < NB; j += NTHR) {
        if (hs[j]) atomicAdd(&g_hist_s[s][j], hs[j]);
        if (hb[j]) atomicAdd(&g_hist_b[s][j], hb[j]);
    }
}

// per-bin mean loss for map m (0=shrink p-bins, 1=binary x-bins)
__device__ __forceinline__ float bin_loss(int m, unsigned long long v, int c) {
    float mean = (float)(v & ((1ULL << CNT_SHIFT) - 1)) * (1.0f / FIXSH) / (float)c;
    if (m == 0) {
        mean = fminf(fmaxf(mean, EPSF), 1.f - EPSF);
        return -__logf(1.f - mean);          // t=0 BCE on p
    } else {
        float l = __logf(1.f + __expf(mean)); // softplus(x) = -log(1-sigmoid(x))
        return fminf(l, 16.118096f);
    }
}

// ---------------- per-sample finalize (OHEM select via histogram) ----------------
__global__ void __launch_bounds__(256) finalize_kernel() {
    const int s = blockIdx.x;
    const int t = threadIdx.x;
    __shared__ int   scnt[256];
    __shared__ float sloss[256];
    __shared__ float res_sel[2];
    __shared__ float res_tot[2];
    __shared__ int   res_totc;

    const int pos = g_pos_cnt[s];

    for (int m = 0; m < 2; m++) {
        const unsigned long long* H = m ? g_hist_b[s] : g_hist_s[s];

        // per-thread partials over 8 bins in DESCENDING score order
        int pc = 0; float pl = 0.f;
#pragma unroll
        for (int i = 0; i < NB / 256; i++) {
            int j = NB - 1 - (t * (NB / 256) + i);
            unsigned long long v = H[j];
            int c = (int)(v >> CNT_SHIFT);
            if (c) { pc += c; pl += bin_loss(m, v, c) * (float)c; }
        }
        scnt[t] = pc; sloss[t] = pl;
        __syncthreads();

        // inclusive scan (Hillis-Steele)
        for (int off = 1; off < 256; off <<= 1) {
            int vc = 0; float vl = 0.f;
            if (t >= off) { vc = scnt[t - off]; vl = sloss[t - off]; }
            __syncthreads();
            if (t >= off) { scnt[t] += vc; sloss[t] += vl; }
            __syncthreads();
        }
        const int   total      = scnt[255];
        const float total_loss = sloss[255];
        const long long neg_num = min((long long)pos * 3, (long long)total);
        const int   excl  = scnt[t] - pc;
        const float lexcl = sloss[t] - pl;

        if (t == 0) { res_tot[m] = total_loss; res_sel[m] = 0.f; if (m == 0) res_totc = total; }
        __syncthreads();

        if (neg_num > 0 && (long long)excl < neg_num && (long long)scnt[t] >= neg_num) {
            long long cum = excl; float sel = lexcl;
#pragma unroll
            for (int i = 0; i < NB / 256; i++) {
                int j = NB - 1 - (t * (NB / 256) + i);
                unsigned long long v = H[j];
                int c = (int)(v >> CNT_SHIFT);
                if (!c) continue;
                float l = bin_loss(m, v, c);
                if (cum + c >= neg_num) {
                    sel += l * (float)(neg_num - cum);   // fractional boundary bin
                    break;
                }
                sel += l * (float)c; cum += c;
            }
            res_sel[m] = sel;
        }
        __syncthreads();
    }

    if (t == 0) {
        const float n = (float)NPIX;
        const long long neg_num = min((long long)pos * 3, (long long)res_totc);
        float L[2];
#pragma unroll
        for (int m = 0; m < 2; m++) {
            const float pl = m ? g_pos_loss_b[s] : g_pos_loss_s[s];
            if (pos > 0 && neg_num > 0)
                L[m] = (pl + res_sel[m]) / (float)(pos + neg_num);
            else
                L[m] = (pl + res_tot[m]) / n;   // all-ones mask path
        }
        g_ls[s] = L[0];
        g_lb[s] = L[1];
        const int tc = g_thr_cnt[s];
        g_lt[s] = (tc > 0) ? g_thr_l1[s] / (float)tc : 0.f;
    }
}

// ---------------- final reduction over batch ----------------
__global__ void output_kernel(float* out, int out_size) {
    if (threadIdx.x == 0) {
        float ss = 0.f, sb = 0.f, st = 0.f;
        for (int i = 0; i < BATCH; i++) { ss += g_ls[i]; sb += g_lb[i]; st += g_lt[i]; }
        ss *= (1.0f / BATCH); sb *= (1.0f / BATCH); st *= (1.0f / BATCH);
        const float all = ss + 1.0f * sb + 10.0f * st;
        if (out_size > 0) out[0] = all;
        if (out_size > 1) out[1] = ss;
        if (out_size > 2) out[2] = sb;
        if (out_size > 3) out[3] = st;
    }
}

extern "C" void kernel_launch(void* const* d_in, const int* in_sizes, int n_in,
                              void* d_out, int out_size) {
    const float* outputs = (const float*)d_in[0];
    const float* gts     = (const float*)d_in[1];
    const float* gtt     = (const float*)d_in[2];

    zero_kernel<<<(BATCH * NB + 511) / 512, 512>>>();
    hist_kernel<<<BATCH * CHUNKS, NTHR>>>(outputs, gts, gtt);
    finalize_kernel<<<BATCH, 256>>>();
    output_kernel<<<1, 32>>>((float*)d_out, out_size);
}

// round 3
// speedup vs baseline: 1.5765x; 1.5765x over previous
#include <cuda_runtime.h>

#define NB      2048
#define NTHR    512
#define BATCH   16
#define NPIX    409600          // 640*640
#define CHUNKS  37
#define CPP     11072           // ceil(NPIX/CHUNKS) rounded to mult of 4; 37*11072 >= NPIX
#define EPSF    1e-7f
#define BPT     (NB / NTHR)     // 4 bins per thread in finalize

// ---------------- device scratch (zero-initialized at load; self-cleaning per run) ----
__device__ unsigned long long g_hist[BATCH][2][NB];   // cnt<<40 | offset_sum
__device__ int   g_pos_cnt[BATCH];
__device__ int   g_thr_cnt[BATCH];
__device__ float g_pos_loss[BATCH][2];
__device__ float g_thr_l1[BATCH];
__device__ float g_res[BATCH][3];                     // ls, lb, lt
__device__ int   g_done[BATCH];
__device__ int   g_done_all;

// decode a global histogram entry -> per-bin mean loss; c = count (>0)
__device__ __forceinline__ float bin_loss(int m, int j, unsigned long long v, int c) {
    float osum = (float)(v & 0xFFFFFFFFFFULL);        // sum of 2^11-scaled in-bin offsets
    float mean = ((float)j + osum * (1.0f / 2048.0f) / (float)c) * (1.0f / (float)NB);
    if (m == 0) {                                     // shrink: p-bins, t=0 BCE = -log(1-p)
        mean = fminf(fmaxf(mean, EPSF), 1.0f - EPSF);
        return -__logf(1.0f - mean);
    } else {                                          // binary: x-bins, softplus(x)
        return __logf(1.0f + __expf(mean));
    }
}

__global__ void __launch_bounds__(NTHR) fused_kernel(const float* __restrict__ outputs,
                                                     const float* __restrict__ gts,
                                                     const float* __restrict__ gtt,
                                                     float* __restrict__ out, int out_size) {
    __shared__ unsigned int hsh[2 * NB];              // 16 KB: [0..NB)=shrink, [NB..2NB)=binary
    __shared__ float sf[3];                           // pos_loss_s, pos_loss_b, thr_l1
    __shared__ int   si[2];                           // pos_cnt, thr_cnt
    __shared__ int   ticket;

    const int s     = blockIdx.x / CHUNKS;
    const int chunk = blockIdx.x % CHUNKS;
    const int tid   = threadIdx.x;

    for (int j = tid; j < 2 * NB; j += NTHR) hsh[j] = 0u;
    if (tid < 3) sf[tid] = 0.f;
    if (tid < 2) si[tid] = 0;
    __syncthreads();

    // ---------------- phase 1: fused streaming pass ----------------
    const int base = chunk * CPP;
    const int nv   = (base < NPIX ? min(CPP, NPIX - base) : 0) >> 2;
    const float4* ps  = (const float4*)(outputs + (size_t)(s * 3 + 0) * NPIX + base);
    const float4* pt  = (const float4*)(outputs + (size_t)(s * 3 + 1) * NPIX + base);
    const float4* pb  = (const float4*)(outputs + (size_t)(s * 3 + 2) * NPIX + base);
    const float4* pgs = (const float4*)(gts + (size_t)s * NPIX + base);
    const float4* pgt = (const float4*)(gtt + (size_t)s * NPIX + base);

    int   pos_cnt = 0, thr_cnt = 0;
    float pls = 0.f, plb = 0.f, tl1 = 0.f;

    for (int i = tid; i < nv; i += NTHR) {
        float4 vs = ps[i], vt = pt[i], vb = pb[i], vgs = pgs[i], vgt = pgt[i];
        const float* fs  = (const float*)&vs;
        const float* ft  = (const float*)&vt;
        const float* fb  = (const float*)&vb;
        const float* fgs = (const float*)&vgs;
        const float* fgt = (const float*)&vgt;
#pragma unroll
        for (int l = 0; l < 4; l++) {
            const float g   = fgs[l];
            const bool  pos = (g > 0.5f);

            // shrink map: score = p
            float p = fminf(fmaxf(fs[l], EPSF), 1.0f - EPSF);
            if (pos) { pos_cnt++; pls -= __logf(p); }
            else {
                float pb_ = p * (float)NB;
                int   b   = min((int)pb_, NB - 1);
                unsigned e = (unsigned)((pb_ - (float)b) * 2048.0f);
                atomicAdd(&hsh[b], (1u << 22) | min(e, 2047u));
            }

            // binary map: score = sigmoid(x), monotone in x -> bin on x
            float x = fb[l];
            if (pos) { plb += __logf(1.0f + __expf(-x)); }
            else {
                float xc  = fminf(fmaxf(x, 0.0f), 0.999999f);
                float xb_ = xc * (float)NB;
                int   b   = min((int)xb_, NB - 1);
                unsigned e = (unsigned)((xb_ - (float)b) * 2048.0f);
                atomicAdd(&hsh[NB + b], (1u << 22) | min(e, 2047u));
            }

            // threshold L1
            const float gt = fgt[l];
            if (gt > 0.f || g > 0.f) { thr_cnt++; tl1 += fabsf(ft[l] - gt); }
        }
    }

    // warp reduce scalars, then shared, then global
#pragma unroll
    for (int off = 16; off; off >>= 1) {
        pos_cnt += __shfl_down_sync(0xffffffffu, pos_cnt, off);
        thr_cnt += __shfl_down_sync(0xffffffffu, thr_cnt, off);
        pls += __shfl_down_sync(0xffffffffu, pls, off);
        plb += __shfl_down_sync(0xffffffffu, plb, off);
        tl1 += __shfl_down_sync(0xffffffffu, tl1, off);
    }
    if ((tid & 31) == 0) {
        atomicAdd(&si[0], pos_cnt); atomicAdd(&si[1], thr_cnt);
        atomicAdd(&sf[0], pls); atomicAdd(&sf[1], plb); atomicAdd(&sf[2], tl1);
    }
    __syncthreads();
    if (tid == 0) {
        atomicAdd(&g_pos_cnt[s], si[0]);
        atomicAdd(&g_thr_cnt[s], si[1]);
        atomicAdd(&g_pos_loss[s][0], sf[0]);
        atomicAdd(&g_pos_loss[s][1], sf[1]);
        atomicAdd(&g_thr_l1[s], sf[2]);
    }

    // merge block histograms to global (u32 -> u64 fields)
    for (int j = tid; j < 2 * NB; j += NTHR) {
        unsigned v = hsh[j];
        if (v) {
            unsigned long long cnt  = v >> 22;
            unsigned long long osum = v & 0x3FFFFFu;
            atomicAdd(&g_hist[s][j >= NB][j & (NB - 1)], (cnt << 40) | osum);
        }
    }

    // ---------------- phase 2: last block of this sample finalizes it ----------------
    __threadfence();
    if (tid == 0) ticket = atomicAdd(&g_done[s], 1);
    __syncthreads();
    if (ticket != CHUNKS - 1) return;

    // reuse hsh as scan arrays
    int*   scnt  = (int*)hsh;            // [NTHR]
    float* sloss = (float*)(hsh + NTHR); // [NTHR]
    __shared__ float fin_sel[2], fin_tot[2];
    __shared__ int   fin_totc;

    const int pos = g_pos_cnt[s];

    for (int m = 0; m < 2; m++) {
        const unsigned long long* H = g_hist[s][m];

        // per-thread partials over BPT bins in DESCENDING score order
        int pc = 0; float pl = 0.f;
#pragma unroll
        for (int i = 0; i < BPT; i++) {
            int j = NB - 1 - (tid * BPT + i);
            unsigned long long v = H[j];
            int c = (int)(v >> 40);
            if (c) { pc += c; pl += bin_loss(m, j, v, c) * (float)c; }
        }
        __syncthreads();   // hsh no longer needed as histogram / prev-iter scan done
        scnt[tid] = pc; sloss[tid] = pl;
        __syncthreads();

        // inclusive Hillis-Steele scan over 512 threads
        for (int off = 1; off < NTHR; off <<= 1) {
            int vc = 0; float vl = 0.f;
            if (tid >= off) { vc = scnt[tid - off]; vl = sloss[tid - off]; }
            __syncthreads();
            if (tid >= off) { scnt[tid] += vc; sloss[tid] += vl; }
            __syncthreads();
        }
        const int   total      = scnt[NTHR - 1];
        const float total_loss = sloss[NTHR - 1];
        const long long neg_num = min((long long)pos * 3, (long long)total);
        const int   excl  = scnt[tid] - pc;
        const float lexcl = sloss[tid] - pl;

        if (tid == 0) { fin_tot[m] = total_loss; fin_sel[m] = 0.f; if (m == 0) fin_totc = total; }
        __syncthreads();

        if (neg_num > 0 && (long long)excl < neg_num && (long long)scnt[tid] >= neg_num) {
            long long cum = excl; float sel = lexcl;
#pragma unroll
            for (int i = 0; i < BPT; i++) {
                int j = NB - 1 - (tid * BPT + i);
                unsigned long long v = H[j];
                int c = (int)(v >> 40);
                if (!c) continue;
                float l = bin_loss(m, j, v, c);
                if (cum + c >= neg_num) { sel += l * (float)(neg_num - cum); break; }
                sel += l * (float)c; cum += c;
            }
            fin_sel[m] = sel;
        }
        __syncthreads();
    }

    // zero this sample's scratch for the next replay
    for (int j = tid; j < 2 * NB; j += NTHR) g_hist[s][j >= NB][j & (NB - 1)] = 0ULL;

    if (tid == 0) {
        const long long neg_num = min((long long)pos * 3, (long long)fin_totc);
        float L[2];
#pragma unroll
        for (int m = 0; m < 2; m++) {
            const float pl = g_pos_loss[s][m];
            if (pos > 0 && neg_num > 0)
                L[m] = (pl + fin_sel[m]) / (float)(pos + neg_num);
            else
                L[m] = (pl + fin_tot[m]) / (float)NPIX;   // all-ones mask path
        }
        const int tc = g_thr_cnt[s];
        g_res[s][0] = L[0];
        g_res[s][1] = L[1];
        g_res[s][2] = (tc > 0) ? g_thr_l1[s] / (float)tc : 0.f;

        // reset per-sample scalar scratch
        g_pos_cnt[s] = 0; g_thr_cnt[s] = 0;
        g_pos_loss[s][0] = 0.f; g_pos_loss[s][1] = 0.f;
        g_thr_l1[s] = 0.f; g_done[s] = 0;

        // ---------------- phase 3: last finalizer writes the output ----------------
        __threadfence();
        if (atomicAdd(&g_done_all, 1) == BATCH - 1) {
            float ss = 0.f, sb = 0.f, st = 0.f;
            for (int i = 0; i < BATCH; i++) {
                ss += g_res[i][0]; sb += g_res[i][1]; st += g_res[i][2];
            }
            ss *= (1.0f / BATCH); sb *= (1.0f / BATCH); st *= (1.0f / BATCH);
            if (out_size > 0) out[0] = ss + 1.0f * sb + 10.0f * st;
            if (out_size > 1) out[1] = ss;
            if (out_size > 2) out[2] = sb;
            if (out_size > 3) out[3] = st;
            g_done_all = 0;
        }
    }
}

extern "C" void kernel_launch(void* const* d_in, const int* in_sizes, int n_in,
                              void* d_out, int out_size) {
    const float* outputs = (const float*)d_in[0];
    const float* gts     = (const float*)d_in[1];
    const float* gtt     = (const float*)d_in[2];
    fused_kernel<<<BATCH * CHUNKS, NTHR>>>(outputs, gts, gtt, (float*)d_out, out_size);
}

// round 4
// speedup vs baseline: 1.8507x; 1.1739x over previous
#include <cuda_runtime.h>

#define NB      2048
#define NTHR    512
#define BATCH   16
#define NPIX    409600          // 640*640
#define CHUNKS  37
#define CPP     11072           // 37*11072 >= NPIX, multiple of 4
#define EPSF    1e-7f
#define BPT     (NB / NTHR)     // 4 bins per thread in finalize

// ---------------- device scratch (zero-initialized at load; self-cleaning per run) ----
__device__ unsigned int g_hist[BATCH][2][NB];   // counts only
__device__ int   g_pos_cnt[BATCH];
__device__ int   g_thr_cnt[BATCH];
__device__ float g_pos_loss[BATCH][2];
__device__ float g_thr_l1[BATCH];
__device__ float g_res[BATCH][3];               // ls, lb, lt
__device__ int   g_done[BATCH];
__device__ int   g_done_all;

// per-bin loss at the bin midpoint; m: 0=shrink (p-bins, -log(1-p)), 1=binary (x-bins, softplus)
__device__ __forceinline__ float bin_loss(int m, int j) {
    float mid = ((float)j + 0.5f) * (1.0f / (float)NB);
    if (m == 0) {
        mid = fminf(mid, 1.0f - EPSF);
        return -__logf(1.0f - mid);
    } else {
        return __logf(1.0f + __expf(mid));
    }
}

__global__ void __launch_bounds__(NTHR, 4) fused_kernel(const float* __restrict__ outputs,
                                                        const float* __restrict__ gts,
                                                        const float* __restrict__ gtt,
                                                        float* __restrict__ out, int out_size) {
    __shared__ unsigned int hsh[2 * NB];        // 16 KB: [0..NB)=shrink, [NB..2NB)=binary
    __shared__ float sf[3];
    __shared__ int   si[2];
    __shared__ int   ticket;

    const int s     = blockIdx.x / CHUNKS;
    const int chunk = blockIdx.x % CHUNKS;
    const int tid   = threadIdx.x;

    for (int j = tid; j < 2 * NB; j += NTHR) hsh[j] = 0u;
    if (tid < 3) sf[tid] = 0.f;
    if (tid < 2) si[tid] = 0;
    __syncthreads();

    // ---------------- phase 1: fused streaming pass ----------------
    const int base = chunk * CPP;
    const int nv   = (base < NPIX ? min(CPP, NPIX - base) : 0) >> 2;
    const float4* ps  = (const float4*)(outputs + (size_t)(s * 3 + 0) * NPIX + base);
    const float4* pt  = (const float4*)(outputs + (size_t)(s * 3 + 1) * NPIX + base);
    const float4* pb  = (const float4*)(outputs + (size_t)(s * 3 + 2) * NPIX + base);
    const float4* pgs = (const float4*)(gts + (size_t)s * NPIX + base);
    const float4* pgt = (const float4*)(gtt + (size_t)s * NPIX + base);

    int   pos_cnt = 0, thr_cnt = 0;
    float pls = 0.f, plb = 0.f, tl1 = 0.f;

    for (int i = tid; i < nv; i += NTHR) {
        float4 vs = ps[i], vt = pt[i], vb = pb[i], vgs = pgs[i], vgt = pgt[i];
        const float* fs  = (const float*)&vs;
        const float* ft  = (const float*)&vt;
        const float* fb  = (const float*)&vb;
        const float* fgs = (const float*)&vgs;
        const float* fgt = (const float*)&vgt;
#pragma unroll
        for (int l = 0; l < 4; l++) {
            const bool pos = (fgs[l] > 0.5f);
            const float p  = fs[l];
            const float x  = fb[l];

            if (pos) {
                pos_cnt++;
                pls -= __logf(fmaxf(p, EPSF));              // -log(p), t=1 BCE
                plb += __logf(1.0f + __expf(-x));           // -log(sigmoid(x))
            } else {
                // shrink: bin on p (uniform in [0,1))
                int b0 = min(max(__float2int_rz(p * (float)NB), 0), NB - 1);
                atomicAdd(&hsh[b0], 1u);
                // binary: sigmoid monotone -> bin on x
                int b1 = min(max(__float2int_rz(x * (float)NB), 0), NB - 1);
                atomicAdd(&hsh[NB + b1], 1u);
            }

            // threshold L1
            const float gt = fgt[l];
            if (gt > 0.f || fgs[l] > 0.f) { thr_cnt++; tl1 += fabsf(ft[l] - gt); }
        }
    }

    // warp reduce scalars, then shared, then global
#pragma unroll
    for (int off = 16; off; off >>= 1) {
        pos_cnt += __shfl_down_sync(0xffffffffu, pos_cnt, off);
        thr_cnt += __shfl_down_sync(0xffffffffu, thr_cnt, off);
        pls += __shfl_down_sync(0xffffffffu, pls, off);
        plb += __shfl_down_sync(0xffffffffu, plb, off);
        tl1 += __shfl_down_sync(0xffffffffu, tl1, off);
    }
    if ((tid & 31) == 0) {
        atomicAdd(&si[0], pos_cnt); atomicAdd(&si[1], thr_cnt);
        atomicAdd(&sf[0], pls); atomicAdd(&sf[1], plb); atomicAdd(&sf[2], tl1);
    }
    __syncthreads();
    if (tid == 0) {
        atomicAdd(&g_pos_cnt[s], si[0]);
        atomicAdd(&g_thr_cnt[s], si[1]);
        atomicAdd(&g_pos_loss[s][0], sf[0]);
        atomicAdd(&g_pos_loss[s][1], sf[1]);
        atomicAdd(&g_thr_l1[s], sf[2]);
    }

    // merge block histograms to global
    for (int j = tid; j < 2 * NB; j += NTHR) {
        unsigned v = hsh[j];
        if (v) atomicAdd(&g_hist[s][j >= NB][j & (NB - 1)], v);
    }

    // ---------------- phase 2: last block of this sample finalizes it ----------------
    __threadfence();
    if (tid == 0) ticket = atomicAdd(&g_done[s], 1);
    __syncthreads();
    if (ticket != CHUNKS - 1) return;

    int*   scnt  = (int*)hsh;            // [NTHR]
    float* sloss = (float*)(hsh + NTHR); // [NTHR]
    __shared__ float fin_sel[2], fin_tot[2];
    __shared__ int   fin_totc;

    const int pos = g_pos_cnt[s];

    for (int m = 0; m < 2; m++) {
        const unsigned int* H = g_hist[s][m];

        // per-thread partials over BPT bins in DESCENDING score order
        int pc = 0; float pl = 0.f;
#pragma unroll
        for (int i = 0; i < BPT; i++) {
            int j = NB - 1 - (tid * BPT + i);
            int c = (int)H[j];
            if (c) { pc += c; pl += bin_loss(m, j) * (float)c; }
        }
        __syncthreads();
        scnt[tid] = pc; sloss[tid] = pl;
        __syncthreads();

        // inclusive Hillis-Steele scan
        for (int off = 1; off < NTHR; off <<= 1) {
            int vc = 0; float vl = 0.f;
            if (tid >= off) { vc = scnt[tid - off]; vl = sloss[tid - off]; }
            __syncthreads();
            if (tid >= off) { scnt[tid] += vc; sloss[tid] += vl; }
            __syncthreads();
        }
        const int   total      = scnt[NTHR - 1];
        const float total_loss = sloss[NTHR - 1];
        const long long neg_num = min((long long)pos * 3, (long long)total);
        const int   excl  = scnt[tid] - pc;
        const float lexcl = sloss[tid] - pl;

        if (tid == 0) { fin_tot[m] = total_loss; fin_sel[m] = 0.f; if (m == 0) fin_totc = total; }
        __syncthreads();

        if (neg_num > 0 && (long long)excl < neg_num && (long long)scnt[tid] >= neg_num) {
            long long cum = excl; float sel = lexcl;
#pragma unroll
            for (int i = 0; i < BPT; i++) {
                int j = NB - 1 - (tid * BPT + i);
                int c = (int)H[j];
                if (!c) continue;
                float l = bin_loss(m, j);
                if (cum + c >= neg_num) { sel += l * (float)(neg_num - cum); break; }
                sel += l * (float)c; cum += c;
            }
            fin_sel[m] = sel;
        }
        __syncthreads();
    }

    // zero this sample's scratch for the next replay
    for (int j = tid; j < 2 * NB; j += NTHR) g_hist[s][j >= NB][j & (NB - 1)] = 0u;

    if (tid == 0) {
        const long long neg_num = min((long long)pos * 3, (long long)fin_totc);
        float L[2];
#pragma unroll
        for (int m = 0; m < 2; m++) {
            const float pl = g_pos_loss[s][m];
            if (pos > 0 && neg_num > 0)
                L[m] = (pl + fin_sel[m]) / (float)(pos + neg_num);
            else
                L[m] = (pl + fin_tot[m]) / (float)NPIX;   // all-ones mask path
        }
        const int tc = g_thr_cnt[s];
        g_res[s][0] = L[0];
        g_res[s][1] = L[1];
        g_res[s][2] = (tc > 0) ? g_thr_l1[s] / (float)tc : 0.f;

        g_pos_cnt[s] = 0; g_thr_cnt[s] = 0;
        g_pos_loss[s][0] = 0.f; g_pos_loss[s][1] = 0.f;
        g_thr_l1[s] = 0.f; g_done[s] = 0;

        // ---------------- phase 3: last finalizer writes the output ----------------
        __threadfence();
        if (atomicAdd(&g_done_all, 1) == BATCH - 1) {
            float ss = 0.f, sb = 0.f, st = 0.f;
            for (int i = 0; i < BATCH; i++) {
                ss += g_res[i][0]; sb += g_res[i][1]; st += g_res[i][2];
            }
            ss *= (1.0f / BATCH); sb *= (1.0f / BATCH); st *= (1.0f / BATCH);
            if (out_size > 0) out[0] = ss + 1.0f * sb + 10.0f * st;
            if (out_size > 1) out[1] = ss;
            if (out_size > 2) out[2] = sb;
            if (out_size > 3) out[3] = st;
            g_done_all = 0;
        }
    }
}

extern "C" void kernel_launch(void* const* d_in, const int* in_sizes, int n_in,
                              void* d_out, int out_size) {
    const float* outputs = (const float*)d_in[0];
    const float* gts     = (const float*)d_in[1];
    const float* gtt     = (const float*)d_in[2];
    fused_kernel<<<BATCH * CHUNKS, NTHR>>>(outputs, gts, gtt, (float*)d_out, out_size);
}

// round 7
// speedup vs baseline: 1.9332x; 1.0446x over previous
#include <cuda_runtime.h>

#define NB      2048
#define NTHR    512
#define BATCH   16
#define NPIX    409600          // 640*640
#define CHUNKS  37
#define CPP     11072           // 37*11072 >= NPIX, multiple of 4
#define EPSF    1e-7f
#define BPT     (NB / NTHR)     // 4 bins per thread in finalize
#define LOG_NB  7.6246189862f   // ln(2048)

// ---------------- device scratch (zero-initialized at load; self-cleaning per run) ----
// hist layout per sample: [0]=neg_s [1]=neg_b [2]=pos_s [3]=pos_b
__device__ unsigned int g_hist[BATCH][4][NB];
__device__ int   g_thr_cnt[BATCH];
__device__ float g_thr_l1[BATCH];
__device__ float g_res[BATCH][3];               // ls, lb, lt
__device__ int   g_done[BATCH];
__device__ int   g_done_all;

// ---- per-bin mean losses (uniform-in-bin analytic means at the divergent bins) ----
__device__ __forceinline__ float loss_neg_s(int j) {       // -log(1-p)
    if (j == NB - 1) return 1.0f + LOG_NB;                 // exact uniform mean of top bin
    return -__logf(1.0f - ((float)j + 0.5f) * (1.0f / (float)NB));
}
__device__ __forceinline__ float loss_pos_s(int j) {       // -log(p)
    if (j == 0) return 1.0f + LOG_NB;                      // exact uniform mean of bottom bin
    return -__logf(((float)j + 0.5f) * (1.0f / (float)NB));
}
__device__ __forceinline__ float loss_neg_b(int j) {       // softplus(x) = -log(1-sigmoid(x))
    return __logf(1.0f + __expf(((float)j + 0.5f) * (1.0f / (float)NB)));
}
__device__ __forceinline__ float loss_pos_b(int j) {       // softplus(-x) = -log(sigmoid(x))
    return __logf(1.0f + __expf(-((float)j + 0.5f) * (1.0f / (float)NB)));
}

__global__ void __launch_bounds__(NTHR, 4) fused_kernel(const float* __restrict__ outputs,
                                                        const float* __restrict__ gts,
                                                        const float* __restrict__ gtt,
                                                        float* __restrict__ out, int out_size) {
    __shared__ unsigned int hsh[4 * NB];        // 32 KB
    __shared__ float sf1;                       // thr_l1
    __shared__ int   si1;                       // thr_cnt
    __shared__ int   ticket;

    // interleaved mapping: adjacent blocks work on different samples
    const int s     = blockIdx.x % BATCH;
    const int chunk = blockIdx.x / BATCH;
    const int tid   = threadIdx.x;

    {   // vectorized zero: 4*NB u32 = 2048 uint4
        uint4* h4 = (uint4*)hsh;
        #pragma unroll
        for (int j = 0; j < (4 * NB / 4) / NTHR; j++)
            h4[j * NTHR + tid] = make_uint4(0u, 0u, 0u, 0u);
    }
    if (tid == 0) { sf1 = 0.f; si1 = 0; }
    __syncthreads();

    // ---------------- phase 1: branch-free streaming pass ----------------
    const int base = chunk * CPP;
    const int nv   = (base < NPIX ? min(CPP, NPIX - base) : 0) >> 2;
    const float4* ps  = (const float4*)(outputs + (size_t)(s * 3 + 0) * NPIX + base);
    const float4* pt  = (const float4*)(outputs + (size_t)(s * 3 + 1) * NPIX + base);
    const float4* pb  = (const float4*)(outputs + (size_t)(s * 3 + 2) * NPIX + base);
    const float4* pgs = (const float4*)(gts + (size_t)s * NPIX + base);
    const float4* pgt = (const float4*)(gtt + (size_t)s * NPIX + base);

    int   thr_cnt = 0;
    float tl1 = 0.f;

    for (int i = tid; i < nv; i += NTHR) {
        float4 vs = ps[i], vt = pt[i], vb = pb[i], vgs = pgs[i], vgt = pgt[i];
        const float* fs  = (const float*)&vs;
        const float* ft  = (const float*)&vt;
        const float* fb  = (const float*)&vb;
        const float* fgs = (const float*)&vgs;
        const float* fgt = (const float*)&vgt;
#pragma unroll
        for (int l = 0; l < 4; l++) {
            const float g  = fgs[l];
            const float gt = fgt[l];
            const bool pos = (g > 0.5f);
            const unsigned off = pos ? 2u * NB : 0u;

            int b0 = min(max(__float2int_rz(fs[l] * (float)NB), 0), NB - 1);
            int b1 = min(max(__float2int_rz(fb[l] * (float)NB), 0), NB - 1);
            atomicAdd(&hsh[off + (unsigned)b0], 1u);
            atomicAdd(&hsh[off + NB + (unsigned)b1], 1u);

            if (pos | (gt > 0.f)) { thr_cnt++; tl1 += fabsf(ft[l] - gt); }
        }
    }

    // reduce the two threshold scalars
#pragma unroll
    for (int off = 16; off; off >>= 1) {
        thr_cnt += __shfl_down_sync(0xffffffffu, thr_cnt, off);
        tl1     += __shfl_down_sync(0xffffffffu, tl1, off);
    }
    if ((tid & 31) == 0) { atomicAdd(&si1, thr_cnt); atomicAdd(&sf1, tl1); }
    __syncthreads();
    if (tid == 0) { atomicAdd(&g_thr_cnt[s], si1); atomicAdd(&g_thr_l1[s], sf1); }

    // merge block histograms to global
    for (int j = tid; j < 4 * NB; j += NTHR) {
        unsigned v = hsh[j];
        if (v) atomicAdd(&((unsigned*)g_hist[s])[j], v);
    }

    // ---------------- phase 2: last block of this sample finalizes it ----------------
    __threadfence();
    if (tid == 0) ticket = atomicAdd(&g_done[s], 1);
    __syncthreads();
    if (ticket != CHUNKS - 1) return;

    int*   scnt  = (int*)hsh;            // [NTHR]
    float* sloss = (float*)(hsh + NTHR); // [NTHR]
    __shared__ float fin_sel[2], fin_tot[2];
    __shared__ int   fin_totc;
    __shared__ float ppos_s, ppos_b;     // positive loss sums
    __shared__ int   ppos_cnt;

    // --- positive-histogram reductions ---
    {
        const unsigned* Hs = g_hist[s][2];
        const unsigned* Hb = g_hist[s][3];
        int   pc = 0; float pls = 0.f, plb = 0.f;
#pragma unroll
        for (int i = 0; i < BPT; i++) {
            int j = tid * BPT + i;
            int cs = (int)Hs[j];
            if (cs) { pc += cs; pls += loss_pos_s(j) * (float)cs; }
            int cb = (int)Hb[j];
            if (cb) { plb += loss_pos_b(j) * (float)cb; }
        }
#pragma unroll
        for (int off = 16; off; off >>= 1) {
            pc  += __shfl_down_sync(0xffffffffu, pc, off);
            pls += __shfl_down_sync(0xffffffffu, pls, off);
            plb += __shfl_down_sync(0xffffffffu, plb, off);
        }
        if (tid == 0) { ppos_cnt = 0; ppos_s = 0.f; ppos_b = 0.f; }
        __syncthreads();
        if ((tid & 31) == 0) {
            atomicAdd(&ppos_cnt, pc);
            atomicAdd(&ppos_s, pls);
            atomicAdd(&ppos_b, plb);
        }
        __syncthreads();
    }
    const int pos = ppos_cnt;

    // --- OHEM selection over negative histograms ---
    for (int m = 0; m < 2; m++) {
        const unsigned* H = g_hist[s][m];

        int pc = 0; float pl = 0.f;
#pragma unroll
        for (int i = 0; i < BPT; i++) {
            int j = NB - 1 - (tid * BPT + i);
            int c = (int)H[j];
            if (c) { pc += c; pl += (m ? loss_neg_b(j) : loss_neg_s(j)) * (float)c; }
        }
        __syncthreads();
        scnt[tid] = pc; sloss[tid] = pl;
        __syncthreads();

        for (int off = 1; off < NTHR; off <<= 1) {
            int vc = 0; float vl = 0.f;
            if (tid >= off) { vc = scnt[tid - off]; vl = sloss[tid - off]; }
            __syncthreads();
            if (tid >= off) { scnt[tid] += vc; sloss[tid] += vl; }
            __syncthreads();
        }
        const int   total      = scnt[NTHR - 1];
        const float total_loss = sloss[NTHR - 1];
        const long long neg_num = min((long long)pos * 3, (long long)total);
        const int   excl  = scnt[tid] - pc;
        const float lexcl = sloss[tid] - pl;

        if (tid == 0) { fin_tot[m] = total_loss; fin_sel[m] = 0.f; if (m == 0) fin_totc = total; }
        __syncthreads();

        if (neg_num > 0 && (long long)excl < neg_num && (long long)scnt[tid] >= neg_num) {
            long long cum = excl; float sel = lexcl;
#pragma unroll
            for (int i = 0; i < BPT; i++) {
                int j = NB - 1 - (tid * BPT + i);
                int c = (int)H[j];
                if (!c) continue;
                float l = m ? loss_neg_b(j) : loss_neg_s(j);
                if (cum + c >= neg_num) { sel += l * (float)(neg_num - cum); break; }
                sel += l * (float)c; cum += c;
            }
            fin_sel[m] = sel;
        }
        __syncthreads();
    }

    // zero this sample's scratch for the next replay
    for (int j = tid; j < 4 * NB; j += NTHR) ((unsigned*)g_hist[s])[j] = 0u;

    if (tid == 0) {
        const long long neg_num = min((long long)pos * 3, (long long)fin_totc);
        float L[2];
#pragma unroll
        for (int m = 0; m < 2; m++) {
            const float pl = m ? ppos_b : ppos_s;
            if (pos > 0 && neg_num > 0)
                L[m] = (pl + fin_sel[m]) / (float)(pos + neg_num);
            else
                L[m] = (pl + fin_tot[m]) / (float)NPIX;   // all-ones mask path
        }
        const int tc = g_thr_cnt[s];
        g_res[s][0] = L[0];
        g_res[s][1] = L[1];
        g_res[s][2] = (tc > 0) ? g_thr_l1[s] / (float)tc : 0.f;

        g_thr_cnt[s] = 0; g_thr_l1[s] = 0.f; g_done[s] = 0;

        // ---------------- phase 3: last finalizer writes the output ----------------
        __threadfence();
        if (atomicAdd(&g_done_all, 1) == BATCH - 1) {
            float ss = 0.f, sb = 0.f, st = 0.f;
            for (int i = 0; i < BATCH; i++) {
                ss += g_res[i][0]; sb += g_res[i][1]; st += g_res[i][2];
            }
            ss *= (1.0f / BATCH); sb *= (1.0f / BATCH); st *= (1.0f / BATCH);
            if (out_size > 0) out[0] = ss + 1.0f * sb + 10.0f * st;
            if (out_size > 1) out[1] = ss;
            if (out_size > 2) out[2] = sb;
            if (out_size > 3) out[3] = st;
            g_done_all = 0;
        }
    }
}

extern "C" void kernel_launch(void* const* d_in, const int* in_sizes, int n_in,
                              void* d_out, int out_size) {
    const float* outputs = (const float*)d_in[0];
    const float* gts     = (const float*)d_in[1];
    const float* gtt     = (const float*)d_in[2];
    fused_kernel<<<BATCH * CHUNKS, NTHR>>>(outputs, gts, gtt, (float*)d_out, out_size);
}

// round 9
// speedup vs baseline: 2.0640x; 1.0677x over previous
#include <cuda_runtime.h>

#define NB      1024
#define NTHR    512
#define BATCH   16
#define NPIX    409600          // 640*640
#define CHUNKS  37
#define CPP     11072           // 37*11072 >= NPIX, multiple of 4
#define EPSF    1e-7f
#define BPT     (NB / NTHR)     // 2 bins per thread in finalize
#define LOG_NB  6.9314718056f   // ln(1024)

// ---------------- device scratch (zero-initialized at load; self-cleaning per run) ----
// hist layout per sample: [0]=neg_s [1]=neg_b [2]=pos_s [3]=pos_b
__device__ unsigned int g_hist[BATCH][4][NB];
__device__ int   g_thr_cnt[BATCH];
__device__ float g_thr_l1[BATCH];
__device__ float g_res[BATCH][3];               // ls, lb, lt
__device__ int   g_done[BATCH];
__device__ int   g_done_all;

// ---- per-bin mean losses (uniform-in-bin analytic means at the divergent bins) ----
__device__ __forceinline__ float loss_neg_s(int j) {       // -log(1-p)
    if (j == NB - 1) return 1.0f + LOG_NB;                 // exact uniform mean of top bin
    return -__logf(1.0f - ((float)j + 0.5f) * (1.0f / (float)NB));
}
__device__ __forceinline__ float loss_pos_s(int j) {       // -log(p)
    if (j == 0) return 1.0f + LOG_NB;                      // exact uniform mean of bottom bin
    return -__logf(((float)j + 0.5f) * (1.0f / (float)NB));
}
__device__ __forceinline__ float loss_neg_b(int j) {       // softplus(x) = -log(1-sigmoid(x))
    return __logf(1.0f + __expf(((float)j + 0.5f) * (1.0f / (float)NB)));
}
__device__ __forceinline__ float loss_pos_b(int j) {       // softplus(-x) = -log(sigmoid(x))
    return __logf(1.0f + __expf(-((float)j + 0.5f) * (1.0f / (float)NB)));
}

__global__ void __launch_bounds__(NTHR, 4) fused_kernel(const float* __restrict__ outputs,
                                                        const float* __restrict__ gts,
                                                        const float* __restrict__ gtt,
                                                        float* __restrict__ out, int out_size) {
    __shared__ unsigned int hsh[4 * NB];        // 16 KB
    __shared__ float sf1;                       // thr_l1
    __shared__ int   si1;                       // thr_cnt
    __shared__ int   ticket;

    // interleaved mapping: adjacent blocks work on different samples
    const int s     = blockIdx.x % BATCH;
    const int chunk = blockIdx.x / BATCH;
    const int tid   = threadIdx.x;

    {   // vectorized zero: 4*NB u32 = 1024 uint4
        uint4* h4 = (uint4*)hsh;
        #pragma unroll
        for (int j = 0; j < (4 * NB / 4) / NTHR; j++)
            h4[j * NTHR + tid] = make_uint4(0u, 0u, 0u, 0u);
    }
    if (tid == 0) { sf1 = 0.f; si1 = 0; }
    __syncthreads();

    // ---------------- phase 1: branch-free streaming pass ----------------
    const int base = chunk * CPP;
    const int nv   = (base < NPIX ? min(CPP, NPIX - base) : 0) >> 2;
    const float4* ps  = (const float4*)(outputs + (size_t)(s * 3 + 0) * NPIX + base);
    const float4* pt  = (const float4*)(outputs + (size_t)(s * 3 + 1) * NPIX + base);
    const float4* pb  = (const float4*)(outputs + (size_t)(s * 3 + 2) * NPIX + base);
    const float4* pgs = (const float4*)(gts + (size_t)s * NPIX + base);
    const float4* pgt = (const float4*)(gtt + (size_t)s * NPIX + base);

    int   thr_cnt = 0;
    float tl1 = 0.f;

    for (int i = tid; i < nv; i += NTHR) {
        float4 vs = ps[i], vt = pt[i], vb = pb[i], vgs = pgs[i], vgt = pgt[i];
        const float* fs  = (const float*)&vs;
        const float* ft  = (const float*)&vt;
        const float* fb  = (const float*)&vb;
        const float* fgs = (const float*)&vgs;
        const float* fgt = (const float*)&vgt;

        // compute all bins + threshold terms first, then fire the atomic burst;
        // ALU work overlaps the ATOMS latency window
        unsigned binA[4], binB[4];
#pragma unroll
        for (int l = 0; l < 4; l++) {
            const unsigned off = (fgs[l] > 0.5f) ? 2u * NB : 0u;
            int b0 = min(max(__float2int_rz(fs[l] * (float)NB), 0), NB - 1);
            int b1 = min(max(__float2int_rz(fb[l] * (float)NB), 0), NB - 1);
            binA[l] = off + (unsigned)b0;
            binB[l] = off + NB + (unsigned)b1;
            const bool sel = (fgs[l] > 0.5f) | (fgt[l] > 0.f);
            if (sel) { thr_cnt++; tl1 += fabsf(ft[l] - fgt[l]); }
        }
#pragma unroll
        for (int l = 0; l < 4; l++) {
            atomicAdd(&hsh[binA[l]], 1u);
            atomicAdd(&hsh[binB[l]], 1u);
        }
    }

    // reduce the two threshold scalars
#pragma unroll
    for (int off = 16; off; off >>= 1) {
        thr_cnt += __shfl_down_sync(0xffffffffu, thr_cnt, off);
        tl1     += __shfl_down_sync(0xffffffffu, tl1, off);
    }
    if ((tid & 31) == 0) { atomicAdd(&si1, thr_cnt); atomicAdd(&sf1, tl1); }
    __syncthreads();
    if (tid == 0) { atomicAdd(&g_thr_cnt[s], si1); atomicAdd(&g_thr_l1[s], sf1); }

    // merge block histograms to global
    for (int j = tid; j < 4 * NB; j += NTHR) {
        unsigned v = hsh[j];
        if (v) atomicAdd(&((unsigned*)g_hist[s])[j], v);
    }

    // ---------------- phase 2: last block of this sample finalizes it ----------------
    __threadfence();
    if (tid == 0) ticket = atomicAdd(&g_done[s], 1);
    __syncthreads();
    if (ticket != CHUNKS - 1) return;

    int*   scnt  = (int*)hsh;            // [NTHR]
    float* sloss = (float*)(hsh + NTHR); // [NTHR]
    __shared__ float fin_sel[2], fin_tot[2];
    __shared__ int   fin_totc;
    __shared__ float ppos_s, ppos_b;     // positive loss sums
    __shared__ int   ppos_cnt;

    // --- positive-histogram reductions ---
    {
        const unsigned* Hs = g_hist[s][2];
        const unsigned* Hb = g_hist[s][3];
        int   pc = 0; float pls = 0.f, plb = 0.f;
#pragma unroll
        for (int i = 0; i < BPT; i++) {
            int j = tid * BPT + i;
            int cs = (int)Hs[j];
            if (cs) { pc += cs; pls += loss_pos_s(j) * (float)cs; }
            int cb = (int)Hb[j];
            if (cb) { plb += loss_pos_b(j) * (float)cb; }
        }
#pragma unroll
        for (int off = 16; off; off >>= 1) {
            pc  += __shfl_down_sync(0xffffffffu, pc, off);
            pls += __shfl_down_sync(0xffffffffu, pls, off);
            plb += __shfl_down_sync(0xffffffffu, plb, off);
        }
        if (tid == 0) { ppos_cnt = 0; ppos_s = 0.f; ppos_b = 0.f; }
        __syncthreads();
        if ((tid & 31) == 0) {
            atomicAdd(&ppos_cnt, pc);
            atomicAdd(&ppos_s, pls);
            atomicAdd(&ppos_b, plb);
        }
        __syncthreads();
    }
    const int pos = ppos_cnt;

    // --- OHEM selection over negative histograms ---
    for (int m = 0; m < 2; m++) {
        const unsigned* H = g_hist[s][m];

        int pc = 0; float pl = 0.f;
#pragma unroll
        for (int i = 0; i < BPT; i++) {
            int j = NB - 1 - (tid * BPT + i);
            int c = (int)H[j];
            if (c) { pc += c; pl += (m ? loss_neg_b(j) : loss_neg_s(j)) * (float)c; }
        }
        __syncthreads();
        scnt[tid] = pc; sloss[tid] = pl;
        __syncthreads();

        for (int off = 1; off < NTHR; off <<= 1) {
            int vc = 0; float vl = 0.f;
            if (tid >= off) { vc = scnt[tid - off]; vl = sloss[tid - off]; }
            __syncthreads();
            if (tid >= off) { scnt[tid] += vc; sloss[tid] += vl; }
            __syncthreads();
        }
        const int   total      = scnt[NTHR - 1];
        const float total_loss = sloss[NTHR - 1];
        const long long neg_num = min((long long)pos * 3, (long long)total);
        const int   excl  = scnt[tid] - pc;
        const float lexcl = sloss[tid] - pl;

        if (tid == 0) { fin_tot[m] = total_loss; fin_sel[m] = 0.f; if (m == 0) fin_totc = total; }
        __syncthreads();

        if (neg_num > 0 && (long long)excl < neg_num && (long long)scnt[tid] >= neg_num) {
            long long cum = excl; float sel = lexcl;
#pragma unroll
            for (int i = 0; i < BPT; i++) {
                int j = NB - 1 - (tid * BPT + i);
                int c = (int)H[j];
                if (!c) continue;
                float l = m ? loss_neg_b(j) : loss_neg_s(j);
                if (cum + c >= neg_num) { sel += l * (float)(neg_num - cum); break; }
                sel += l * (float)c; cum += c;
            }
            fin_sel[m] = sel;
        }
        __syncthreads();
    }

    // zero this sample's scratch for the next replay
    for (int j = tid; j < 4 * NB; j += NTHR) ((unsigned*)g_hist[s])[j] = 0u;

    if (tid == 0) {
        const long long neg_num = min((long long)pos * 3, (long long)fin_totc);
        float L[2];
#pragma unroll
        for (int m = 0; m < 2; m++) {
            const float pl = m ? ppos_b : ppos_s;
            if (pos > 0 && neg_num > 0)
                L[m] = (pl + fin_sel[m]) / (float)(pos + neg_num);
            else
                L[m] = (pl + fin_tot[m]) / (float)NPIX;   // all-ones mask path
        }
        const int tc = g_thr_cnt[s];
        g_res[s][0] = L[0];
        g_res[s][1] = L[1];
        g_res[s][2] = (tc > 0) ? g_thr_l1[s] / (float)tc : 0.f;

        g_thr_cnt[s] = 0; g_thr_l1[s] = 0.f; g_done[s] = 0;

        // ---------------- phase 3: last finalizer writes the output ----------------
        __threadfence();
        if (atomicAdd(&g_done_all, 1) == BATCH - 1) {
            float ss = 0.f, sb = 0.f, st = 0.f;
            for (int i = 0; i < BATCH; i++) {
                ss += g_res[i][0]; sb += g_res[i][1]; st += g_res[i][2];
            }
            ss *= (1.0f / BATCH); sb *= (1.0f / BATCH); st *= (1.0f / BATCH);
            if (out_size > 0) out[0] = ss + 1.0f * sb + 10.0f * st;
            if (out_size > 1) out[1] = ss;
            if (out_size > 2) out[2] = sb;
            if (out_size > 3) out[3] = st;
            g_done_all = 0;
        }
    }
}

extern "C" void kernel_launch(void* const* d_in, const int* in_sizes, int n_in,
                              void* d_out, int out_size) {
    const float* outputs = (const float*)d_in[0];
    const float* gts     = (const float*)d_in[1];
    const float* gtt     = (const float*)d_in[2];
    fused_kernel<<<BATCH * CHUNKS, NTHR>>>(outputs, gts, gtt, (float*)d_out, out_size);
}

// round 16
// speedup vs baseline: 2.1692x; 1.0510x over previous
#include <cuda_runtime.h>

#define NB      512
#define NTHR    512
#define BATCH   16
#define NPIX    409600          // 640*640
#define CHUNKS  37
#define CPP     11072           // 37*11072 >= NPIX, multiple of 4
#define EPSF    1e-7f
#define LOG_NB  6.2383246250f   // ln(512)

// ---------------- device scratch (zero-initialized at load; self-cleaning per run) ----
// hist layout per sample: [0]=neg_s [1]=neg_b [2]=pos_s [3]=pos_b
__device__ unsigned int g_hist[BATCH][4][NB];
__device__ int   g_thr_cnt[BATCH];
__device__ float g_thr_l1[BATCH];
__device__ float g_res[BATCH][3];               // ls, lb, lt
__device__ int   g_done[BATCH];
__device__ int   g_done_all;

// ---- per-bin mean losses (uniform-in-bin analytic means at the divergent bins) ----
__device__ __forceinline__ float loss_neg_s(int j) {       // -log(1-p)
    if (j == NB - 1) return 1.0f + LOG_NB;                 // exact uniform mean of top bin
    return -__logf(1.0f - ((float)j + 0.5f) * (1.0f / (float)NB));
}
__device__ __forceinline__ float loss_pos_s(int j) {       // -log(p)
    if (j == 0) return 1.0f + LOG_NB;                      // exact uniform mean of bottom bin
    return -__logf(((float)j + 0.5f) * (1.0f / (float)NB));
}
__device__ __forceinline__ float loss_neg_b(int j) {       // softplus(x) = -log(1-sigmoid(x))
    return __logf(1.0f + __expf(((float)j + 0.5f) * (1.0f / (float)NB)));
}
__device__ __forceinline__ float loss_pos_b(int j) {       // softplus(-x) = -log(sigmoid(x))
    return __logf(1.0f + __expf(-((float)j + 0.5f) * (1.0f / (float)NB)));
}

__global__ void __launch_bounds__(NTHR, 4) fused_kernel(const float* __restrict__ outputs,
                                                        const float* __restrict__ gts,
                                                        const float* __restrict__ gtt,
                                                        float* __restrict__ out, int out_size) {
    __shared__ unsigned int hsh[4 * NB];        // 8 KB: [0]=neg_s [1]=neg_b [2]=pos_s [3]=pos_b
    __shared__ float sf1;                       // thr_l1
    __shared__ int   si1;                       // thr_cnt
    __shared__ int   ticket;

    // interleaved mapping: adjacent blocks work on different samples
    const int s     = blockIdx.x % BATCH;
    const int chunk = blockIdx.x / BATCH;
    const int tid   = threadIdx.x;

    {   // vectorized zero: 4*NB u32 = 512 uint4
        uint4* h4 = (uint4*)hsh;
        h4[tid] = make_uint4(0u, 0u, 0u, 0u);
    }
    if (tid == 0) { sf1 = 0.f; si1 = 0; }
    __syncthreads();

    // ---------------- phase 1: branch-free streaming pass ----------------
    const int base = chunk * CPP;
    const int nv   = (base < NPIX ? min(CPP, NPIX - base) : 0) >> 2;
    const float4* ps  = (const float4*)(outputs + (size_t)(s * 3 + 0) * NPIX + base);
    const float4* pt  = (const float4*)(outputs + (size_t)(s * 3 + 1) * NPIX + base);
    const float4* pb  = (const float4*)(outputs + (size_t)(s * 3 + 2) * NPIX + base);
    const float4* pgs = (const float4*)(gts + (size_t)s * NPIX + base);
    const float4* pgt = (const float4*)(gtt + (size_t)s * NPIX + base);

    int   thr_cnt = 0;
    float tl1 = 0.f;

    for (int i = tid; i < nv; i += NTHR) {
        float4 vs = ps[i], vt = pt[i], vb = pb[i], vgs = pgs[i], vgt = pgt[i];
        const float* fs  = (const float*)&vs;
        const float* ft  = (const float*)&vt;
        const float* fb  = (const float*)&vb;
        const float* fgs = (const float*)&vgs;
        const float* fgt = (const float*)&vgt;

        // compute all bins + threshold terms first, then fire the atomic burst
        unsigned binA[4], binB[4];
#pragma unroll
        for (int l = 0; l < 4; l++) {
            const unsigned off = (fgs[l] > 0.5f) ? 2u * NB : 0u;
            int b0 = min(max(__float2int_rz(fs[l] * (float)NB), 0), NB - 1);
            int b1 = min(max(__float2int_rz(fb[l] * (float)NB), 0), NB - 1);
            binA[l] = off + (unsigned)b0;
            binB[l] = off + NB + (unsigned)b1;
            const bool sel = (fgs[l] > 0.5f) | (fgt[l] > 0.f);
            if (sel) { thr_cnt++; tl1 += fabsf(ft[l] - fgt[l]); }
        }
#pragma unroll
        for (int l = 0; l < 4; l++) {
            atomicAdd(&hsh[binA[l]], 1u);
            atomicAdd(&hsh[binB[l]], 1u);
        }
    }

    // reduce the two threshold scalars
#pragma unroll
    for (int off = 16; off; off >>= 1) {
        thr_cnt += __shfl_down_sync(0xffffffffu, thr_cnt, off);
        tl1     += __shfl_down_sync(0xffffffffu, tl1, off);
    }
    if ((tid & 31) == 0) { atomicAdd(&si1, thr_cnt); atomicAdd(&sf1, tl1); }
    __syncthreads();
    if (tid == 0) { atomicAdd(&g_thr_cnt[s], si1); atomicAdd(&g_thr_l1[s], sf1); }

    // merge block histograms to global
    for (int j = tid; j < 4 * NB; j += NTHR) {
        unsigned v = hsh[j];
        if (v) atomicAdd(&((unsigned*)g_hist[s])[j], v);
    }

    // ---------------- phase 2: last block of this sample finalizes it ----------------
    __threadfence();
    if (tid == 0) ticket = atomicAdd(&g_done[s], 1);
    __syncthreads();
    if (ticket != CHUNKS - 1) return;

    int*   scnt  = (int*)hsh;            // [NTHR]
    float* sloss = (float*)(hsh + NTHR); // [NTHR]
    __shared__ float fin_sel[2], fin_tot[2];
    __shared__ int   fin_totc;
    __shared__ float ppos_s, ppos_b;     // positive loss sums
    __shared__ int   ppos_cnt;

    // --- positive-histogram reductions (1 bin per thread) ---
    {
        int   pc = 0; float pls = 0.f, plb = 0.f;
        {
            int cs = (int)g_hist[s][2][tid];
            if (cs) { pc += cs; pls += loss_pos_s(tid) * (float)cs; }
            int cb = (int)g_hist[s][3][tid];
            if (cb) { plb += loss_pos_b(tid) * (float)cb; }
        }
#pragma unroll
        for (int off = 16; off; off >>= 1) {
            pc  += __shfl_down_sync(0xffffffffu, pc, off);
            pls += __shfl_down_sync(0xffffffffu, pls, off);
            plb += __shfl_down_sync(0xffffffffu, plb, off);
        }
        if (tid == 0) { ppos_cnt = 0; ppos_s = 0.f; ppos_b = 0.f; }
        __syncthreads();
        if ((tid & 31) == 0) {
            atomicAdd(&ppos_cnt, pc);
            atomicAdd(&ppos_s, pls);
            atomicAdd(&ppos_b, plb);
        }
        __syncthreads();
    }
    const int pos = ppos_cnt;

    // --- OHEM selection over negative histograms (1 bin per thread, descending) ---
    for (int m = 0; m < 2; m++) {
        const unsigned* H = g_hist[s][m];
        const int j = NB - 1 - tid;          // descending score order
        const int pc = (int)H[j];
        const float pl = pc ? (m ? loss_neg_b(j) : loss_neg_s(j)) * (float)pc : 0.f;

        __syncthreads();
        scnt[tid] = pc; sloss[tid] = pl;
        __syncthreads();

        for (int off = 1; off < NTHR; off <<= 1) {
            int vc = 0; float vl = 0.f;
            if (tid >= off) { vc = scnt[tid - off]; vl = sloss[tid - off]; }
            __syncthreads();
            if (tid >= off) { scnt[tid] += vc; sloss[tid] += vl; }
            __syncthreads();
        }
        const int   total      = scnt[NTHR - 1];
        const float total_loss = sloss[NTHR - 1];
        const long long neg_num = min((long long)pos * 3, (long long)total);
        const int   excl  = scnt[tid] - pc;

        if (tid == 0) { fin_tot[m] = total_loss; fin_sel[m] = 0.f; if (m == 0) fin_totc = total; }
        __syncthreads();

        // the single boundary thread computes selected = prefix_excl + fractional own bin
        if (neg_num > 0 && (long long)excl < neg_num && (long long)scnt[tid] >= neg_num) {
            float sel = sloss[tid] - pl;     // loss of all higher-score bins
            float l = m ? loss_neg_b(j) : loss_neg_s(j);
            sel += l * (float)(neg_num - (long long)excl);   // fractional boundary bin
            fin_sel[m] = sel;
        }
        __syncthreads();
    }

    // zero this sample's scratch for the next replay (4*NB u32 = 2048)
    for (int j = tid; j < 4 * NB; j += NTHR) ((unsigned*)g_hist[s])[j] = 0u;

    if (tid == 0) {
        const long long neg_num = min((long long)pos * 3, (long long)fin_totc);
        float L[2];
#pragma unroll
        for (int m = 0; m < 2; m++) {
            const float pl = m ? ppos_b : ppos_s;
            if (pos > 0 && neg_num > 0)
                L[m] = (pl + fin_sel[m]) / (float)(pos + neg_num);
            else
                L[m] = (pl + fin_tot[m]) / (float)NPIX;   // all-ones mask path
        }
        const int tc = g_thr_cnt[s];
        g_res[s][0] = L[0];
        g_res[s][1] = L[1];
        g_res[s][2] = (tc > 0) ? g_thr_l1[s] / (float)tc : 0.f;

        g_thr_cnt[s] = 0; g_thr_l1[s] = 0.f; g_done[s] = 0;

        // ---------------- phase 3: last finalizer writes the output ----------------
        __threadfence();
        if (atomicAdd(&g_done_all, 1) == BATCH - 1) {
            float ss = 0.f, sb = 0.f, st = 0.f;
            for (int i = 0; i < BATCH; i++) {
                ss += g_res[i][0]; sb += g_res[i][1]; st += g_res[i][2];
            }
            ss *= (1.0f / BATCH); sb *= (1.0f / BATCH); st *= (1.0f / BATCH);
            if (out_size > 0) out[0] = ss + 1.0f * sb + 10.0f * st;
            if (out_size > 1) out[1] = ss;
            if (out_size > 2) out[2] = sb;
            if (out_size > 3) out[3] = st;
            g_done_all = 0;
        }
    }
}

extern "C" void kernel_launch(void* const* d_in, const int* in_sizes, int n_in,
                              void* d_out, int out_size) {
    const float* outputs = (const float*)d_in[0];
    const float* gts     = (const float*)d_in[1];
    const float* gtt     = (const float*)d_in[2];
    fused_kernel<<<BATCH * CHUNKS, NTHR>>>(outputs, gts, gtt, (float*)d_out, out_size);
}